// round 15
// baseline (speedup 1.0000x reference)
#include <cuda_runtime.h>
#include <math.h>

#define N_BATCH 32
#define C_IN    256
#define C_SQ    64
#define HW      12544              // 112*112
#define HW4     3136               // HW/4 float4 per plane
#define PLANES  (N_BATCH * C_IN)   // 8192
#define TPB     448                // 448 * 7 == 3136 exactly
#define VPT     7                  // float4 per thread (scale kernel)

#define GROUPS      4
#define BATCH_PER_G (N_BATCH / GROUPS)        // 8
#define PLANES_PER_G (BATCH_PER_G * C_IN)     // 2048

// Scratch (no allocations allowed)
__device__ float g_pool[PLANES];
__device__ float g_gate[PLANES];

// ---------------------------------------------------------------------------
// Pool: one block per plane in the group, 256 threads, strided float4 loop.
// ---------------------------------------------------------------------------
__global__ __launch_bounds__(256) void se_pool_kernel(
    const float* __restrict__ x, int plane_base)
{
    const int plane = plane_base + blockIdx.x;
    const float4* p = reinterpret_cast<const float4*>(x + (size_t)plane * HW);

    float sum = 0.0f;
    #pragma unroll 4
    for (int i = threadIdx.x; i < HW4; i += 256) {
        float4 v = p[i];
        sum += (v.x + v.y) + (v.z + v.w);
    }

    #pragma unroll
    for (int off = 16; off > 0; off >>= 1)
        sum += __shfl_down_sync(0xFFFFFFFFu, sum, off);

    __shared__ float warp_sums[8];
    const int lane = threadIdx.x & 31;
    const int wid  = threadIdx.x >> 5;
    if (lane == 0) warp_sums[wid] = sum;
    __syncthreads();

    if (wid == 0) {
        float s = (lane < 8) ? warp_sums[lane] : 0.0f;
        #pragma unroll
        for (int off = 4; off > 0; off >>= 1)
            s += __shfl_down_sync(0xFFFFFFFFu, s, off);
        if (lane == 0)
            g_pool[plane] = s * (1.0f / (float)HW);
    }
}

// ---------------------------------------------------------------------------
// MLP: one block per batch in the group.
// ---------------------------------------------------------------------------
__global__ __launch_bounds__(256) void se_mlp_kernel(
    const float* __restrict__ w_reduce,   // [C_SQ, C_IN]
    const float* __restrict__ b_reduce,   // [C_SQ]
    const float* __restrict__ w_expand,   // [C_IN, C_SQ]
    const float* __restrict__ b_expand,   // [C_IN]
    int batch_base)
{
    const int n   = batch_base + blockIdx.x;
    const int tid = threadIdx.x;

    __shared__ float s_in[C_IN];
    __shared__ float s_red[C_SQ];

    s_in[tid] = g_pool[n * C_IN + tid];
    __syncthreads();

    if (tid < C_SQ) {
        float acc = b_reduce[tid];
        const float* wr = w_reduce + tid * C_IN;
        #pragma unroll 8
        for (int c = 0; c < C_IN; c++)
            acc = fmaf(wr[c], s_in[c], acc);
        s_red[tid] = fmaxf(acc, 0.0f);
    }
    __syncthreads();

    float acc = b_expand[tid];
    const float* we = w_expand + tid * C_SQ;
    #pragma unroll 8
    for (int k = 0; k < C_SQ; k++)
        acc = fmaf(we[k], s_red[k], acc);

    g_gate[n * C_IN + tid] = 1.0f / (1.0f + __expf(-acc));
}

// ---------------------------------------------------------------------------
// Scale: one block per plane in the group, reversed within the group (pool's
// most recent reads are L2-hot). 448x7 front-batched loads, streaming stores.
// ---------------------------------------------------------------------------
__global__ __launch_bounds__(TPB) void se_scale_kernel(
    const float* __restrict__ x,
    float*       __restrict__ out,
    int plane_base)
{
    const int plane = plane_base + (PLANES_PER_G - 1) - blockIdx.x;
    const float g = __ldg(&g_gate[plane]);

    const float4* p = reinterpret_cast<const float4*>(x   + (size_t)plane * HW);
    float4*       q = reinterpret_cast<float4*>(out       + (size_t)plane * HW);

    float4 v[VPT];
    #pragma unroll
    for (int i = 0; i < VPT; i++)
        v[i] = p[threadIdx.x + i * TPB];

    #pragma unroll
    for (int i = 0; i < VPT; i++) {
        v[i].x *= g; v[i].y *= g; v[i].z *= g; v[i].w *= g;
        __stcs(&q[threadIdx.x + i * TPB], v[i]);
    }
}

// ---------------------------------------------------------------------------
// Two-stream pipelined launch: stream1 = pool+mlp per group, stream2 = scale
// per group (gated by events). scale(g) overlaps pool(g+1), so launch
// boundaries and wave tails of one stream are covered by the other.
// ---------------------------------------------------------------------------
extern "C" void kernel_launch(void* const* d_in, const int* in_sizes, int n_in,
                              void* d_out, int out_size)
{
    const float* x        = (const float*)d_in[0];
    const float* w_reduce = (const float*)d_in[1];
    const float* b_reduce = (const float*)d_in[2];
    const float* w_expand = (const float*)d_in[3];
    const float* b_expand = (const float*)d_in[4];
    float* out = (float*)d_out;

    // Host-side stream/event objects, created once and reused every call
    // (identical captured work each call; no device memory involved).
    static cudaStream_t s1 = nullptr, s2 = nullptr;
    static cudaEvent_t  ev_start, ev_g[GROUPS], ev_s1_done, ev_s2_done;
    static bool init = false;
    if (!init) {
        cudaStreamCreateWithFlags(&s1, cudaStreamNonBlocking);
        cudaStreamCreateWithFlags(&s2, cudaStreamNonBlocking);
        cudaEventCreateWithFlags(&ev_start,   cudaEventDisableTiming);
        for (int g = 0; g < GROUPS; g++)
            cudaEventCreateWithFlags(&ev_g[g], cudaEventDisableTiming);
        cudaEventCreateWithFlags(&ev_s1_done, cudaEventDisableTiming);
        cudaEventCreateWithFlags(&ev_s2_done, cudaEventDisableTiming);
        init = true;
    }

    // Fork both worker streams off the (captured) default stream.
    cudaEventRecord(ev_start, 0);
    cudaStreamWaitEvent(s1, ev_start, 0);
    cudaStreamWaitEvent(s2, ev_start, 0);

    for (int g = 0; g < GROUPS; g++) {
        const int plane_base = g * PLANES_PER_G;
        const int batch_base = g * BATCH_PER_G;

        se_pool_kernel<<<PLANES_PER_G, 256, 0, s1>>>(x, plane_base);
        se_mlp_kernel<<<BATCH_PER_G, 256, 0, s1>>>(w_reduce, b_reduce,
                                                   w_expand, b_expand,
                                                   batch_base);
        cudaEventRecord(ev_g[g], s1);
        cudaStreamWaitEvent(s2, ev_g[g], 0);
        se_scale_kernel<<<PLANES_PER_G, TPB, 0, s2>>>(x, out, plane_base);
    }

    // Join both streams back into the default stream.
    cudaEventRecord(ev_s1_done, s1);
    cudaEventRecord(ev_s2_done, s2);
    cudaStreamWaitEvent(0, ev_s1_done, 0);
    cudaStreamWaitEvent(0, ev_s2_done, 0);
}

// round 16
// speedup vs baseline: 1.1961x; 1.1961x over previous
#include <cuda_runtime.h>
#include <math.h>

#define N_BATCH 32
#define C_IN    256
#define C_SQ    64
#define HW      12544              // floats per plane (112*112)
#define HW4     3136               // float4 per plane = 32 lanes * 98
#define F4_PER_LANE 98             // 3136 / 32
#define PLANES  (N_BATCH * C_IN)   // 8192
#define TPB     448
#define NBLK    296                // 2/SM x 148 SMs (fits 152-SM GB300 too)
#define NWARPS  (NBLK * (TPB / 32))   // 4144 warps total

// Scratch (no allocations). Zero-initialized.
__device__ float    g_pool[PLANES];
__device__ float    g_gate[PLANES];
__device__ unsigned g_bar_count;
__device__ unsigned g_bar_gen;

__device__ __forceinline__ unsigned ld_acquire_gpu(const unsigned* p) {
    unsigned v;
    asm volatile("ld.acquire.gpu.u32 %0, [%1];" : "=r"(v) : "l"(p) : "memory");
    return v;
}

// Sense-reversing grid barrier (proven in R11). Grid fully resident.
__device__ __forceinline__ void grid_barrier() {
    __syncthreads();
    if (threadIdx.x == 0) {
        __threadfence();
        unsigned gen = ld_acquire_gpu(&g_bar_gen);
        unsigned old = atomicAdd(&g_bar_count, 1u);
        if (old == NBLK - 1u) {
            g_bar_count = 0u;
            __threadfence();
            atomicAdd(&g_bar_gen, 1u);
        } else {
            while (ld_acquire_gpu(&g_bar_gen) == gen)
                __nanosleep(32);
        }
    }
    __syncthreads();
}

// ---------------------------------------------------------------------------
// Persistent kernel, warp-autonomous phases:
//   phase 1: each warp reduces whole planes (no block syncs)
//   phase 2: blocks 0..31 compute the MLP
//   phase 3: each warp scales whole planes in reverse order (no block syncs)
// ---------------------------------------------------------------------------
__global__ __launch_bounds__(TPB, 2) void se_persistent_kernel(
    const float* __restrict__ x,
    float*       __restrict__ out,
    const float* __restrict__ w_reduce,   // [C_SQ, C_IN]
    const float* __restrict__ b_reduce,   // [C_SQ]
    const float* __restrict__ w_expand,   // [C_IN, C_SQ]
    const float* __restrict__ b_expand)   // [C_IN]
{
    const int tid  = threadIdx.x;
    const int lane = tid & 31;
    const int wid  = tid >> 5;
    const int gw   = blockIdx.x * (TPB / 32) + wid;   // global warp id

    // ---------------- Phase 1: pool, one warp per plane ----------------
    for (int plane = gw; plane < PLANES; plane += NWARPS) {
        const float4* p = reinterpret_cast<const float4*>(x + (size_t)plane * HW);

        float s0 = 0.0f, s1 = 0.0f;
        #pragma unroll 7
        for (int i = 0; i < F4_PER_LANE; i += 2) {
            float4 a = p[lane + (i    ) * 32];
            float4 b = p[lane + (i + 1) * 32];
            s0 += (a.x + a.y) + (a.z + a.w);
            s1 += (b.x + b.y) + (b.z + b.w);
        }
        float sum = s0 + s1;

        #pragma unroll
        for (int off = 16; off > 0; off >>= 1)
            sum += __shfl_down_sync(0xFFFFFFFFu, sum, off);

        if (lane == 0)
            g_pool[plane] = sum * (1.0f / (float)HW);
    }

    grid_barrier();

    // ---------------- Phase 2: MLP (blocks 0..31, one batch each) ------
    if (blockIdx.x < N_BATCH) {
        const int n = blockIdx.x;
        __shared__ float s_in[C_IN];
        __shared__ float s_red[C_SQ];

        if (tid < C_IN) s_in[tid] = __ldcg(&g_pool[n * C_IN + tid]);
        __syncthreads();

        if (tid < C_SQ) {
            float a0 = b_reduce[tid], a1 = 0.f, a2 = 0.f, a3 = 0.f;
            const float* wr = w_reduce + tid * C_IN;
            #pragma unroll 4
            for (int k = 0; k < C_IN; k += 4) {
                a0 = fmaf(wr[k + 0], s_in[k + 0], a0);
                a1 = fmaf(wr[k + 1], s_in[k + 1], a1);
                a2 = fmaf(wr[k + 2], s_in[k + 2], a2);
                a3 = fmaf(wr[k + 3], s_in[k + 3], a3);
            }
            s_red[tid] = fmaxf((a0 + a1) + (a2 + a3), 0.0f);
        }
        __syncthreads();

        if (tid < C_IN) {
            float acc = b_expand[tid];
            const float* we = w_expand + tid * C_SQ;
            #pragma unroll 8
            for (int k = 0; k < C_SQ; k++)
                acc = fmaf(we[k], s_red[k], acc);
            g_gate[n * C_IN + tid] = 1.0f / (1.0f + __expf(-acc));
        }
    }

    grid_barrier();

    // ---------------- Phase 3: scale, one warp per plane, reversed -----
    for (int idx = gw; idx < PLANES; idx += NWARPS) {
        const int plane = (PLANES - 1) - idx;          // L2 tail reuse
        const float g = __ldcg(&g_gate[plane]);

        const float4* p = reinterpret_cast<const float4*>(x   + (size_t)plane * HW);
        float4*       q = reinterpret_cast<float4*>(out       + (size_t)plane * HW);

        #pragma unroll 7
        for (int i = 0; i < F4_PER_LANE; i++) {
            float4 v = p[lane + i * 32];
            v.x *= g; v.y *= g; v.z *= g; v.w *= g;
            __stcs(&q[lane + i * 32], v);
        }
    }
}

// ---------------------------------------------------------------------------
extern "C" void kernel_launch(void* const* d_in, const int* in_sizes, int n_in,
                              void* d_out, int out_size)
{
    const float* x        = (const float*)d_in[0];
    const float* w_reduce = (const float*)d_in[1];
    const float* b_reduce = (const float*)d_in[2];
    const float* w_expand = (const float*)d_in[3];
    const float* b_expand = (const float*)d_in[4];
    float* out = (float*)d_out;

    se_persistent_kernel<<<NBLK, TPB>>>(x, out, w_reduce, b_reduce,
                                        w_expand, b_expand);
}

// round 17
// speedup vs baseline: 1.2143x; 1.0152x over previous
#include <cuda_runtime.h>
#include <math.h>

#define N_BATCH 32
#define C_IN    256
#define C_SQ    64
#define HW      12544              // floats per plane (112*112)
#define HW4     3136               // float4 per plane
#define PLANES  (N_BATCH * C_IN)   // 8192
#define TPB     256
#define BPSM    6
#define NBLK    (BPSM * 148)       // 888, fully resident (152-SM GB300 too)

// Scratch (no allocations). Zero-initialized.
__device__ float    g_pool[PLANES];
__device__ float    g_gate[PLANES];
__device__ unsigned g_bar_count;
__device__ unsigned g_bar_gen;

__device__ __forceinline__ unsigned ld_acquire_gpu(const unsigned* p) {
    unsigned v;
    asm volatile("ld.acquire.gpu.u32 %0, [%1];" : "=r"(v) : "l"(p) : "memory");
    return v;
}

// Sense-reversing grid barrier; grid fully resident by construction.
__device__ __forceinline__ void grid_barrier() {
    __syncthreads();
    if (threadIdx.x == 0) {
        __threadfence();
        unsigned gen = ld_acquire_gpu(&g_bar_gen);
        unsigned old = atomicAdd(&g_bar_count, 1u);
        if (old == (unsigned)(NBLK - 1)) {
            g_bar_count = 0u;
            __threadfence();
            atomicAdd(&g_bar_gen, 1u);
        } else {
            while (ld_acquire_gpu(&g_bar_gen) == gen)
                __nanosleep(32);
        }
    }
    __syncthreads();
}

// ---------------------------------------------------------------------------
// Persistent kernel at 48 warps/SM. Phases mirror the proven standalone
// kernels exactly (block-per-plane), with grid barriers replacing launches.
// ---------------------------------------------------------------------------
__global__ __launch_bounds__(TPB, BPSM) void se_persistent_kernel(
    const float* __restrict__ x,
    float*       __restrict__ out,
    const float* __restrict__ w_reduce,   // [C_SQ, C_IN]
    const float* __restrict__ b_reduce,   // [C_SQ]
    const float* __restrict__ w_expand,   // [C_IN, C_SQ]
    const float* __restrict__ b_expand)   // [C_IN]
{
    const int tid  = threadIdx.x;
    const int lane = tid & 31;
    const int wid  = tid >> 5;

    __shared__ float warp_sums[TPB / 32];   // 8

    // ---------------- Phase 1: pool (block-per-plane, strided loop) ----------
    for (int plane = blockIdx.x; plane < PLANES; plane += NBLK) {
        const float4* p = reinterpret_cast<const float4*>(x + (size_t)plane * HW);

        float sum = 0.0f;
        #pragma unroll 4
        for (int i = tid; i < HW4; i += TPB) {
            float4 v = p[i];
            sum += (v.x + v.y) + (v.z + v.w);
        }

        #pragma unroll
        for (int off = 16; off > 0; off >>= 1)
            sum += __shfl_down_sync(0xFFFFFFFFu, sum, off);

        if (lane == 0) warp_sums[wid] = sum;
        __syncthreads();

        if (wid == 0) {
            float s = (lane < TPB / 32) ? warp_sums[lane] : 0.0f;
            #pragma unroll
            for (int off = 4; off > 0; off >>= 1)
                s += __shfl_down_sync(0xFFFFFFFFu, s, off);
            if (lane == 0)
                g_pool[plane] = s * (1.0f / (float)HW);
        }
        __syncthreads();
    }

    grid_barrier();

    // ---------------- Phase 2: MLP (blocks 0..31, one batch each) ------------
    if (blockIdx.x < N_BATCH) {
        const int n = blockIdx.x;
        __shared__ float s_in[C_IN];
        __shared__ float s_red[C_SQ];

        s_in[tid] = __ldcg(&g_pool[n * C_IN + tid]);
        __syncthreads();

        if (tid < C_SQ) {
            float a0 = b_reduce[tid], a1 = 0.f, a2 = 0.f, a3 = 0.f;
            const float* wr = w_reduce + tid * C_IN;
            #pragma unroll 4
            for (int k = 0; k < C_IN; k += 4) {
                a0 = fmaf(wr[k + 0], s_in[k + 0], a0);
                a1 = fmaf(wr[k + 1], s_in[k + 1], a1);
                a2 = fmaf(wr[k + 2], s_in[k + 2], a2);
                a3 = fmaf(wr[k + 3], s_in[k + 3], a3);
            }
            s_red[tid] = fmaxf((a0 + a1) + (a2 + a3), 0.0f);
        }
        __syncthreads();

        float acc = b_expand[tid];
        const float* we = w_expand + tid * C_SQ;
        #pragma unroll 8
        for (int k = 0; k < C_SQ; k++)
            acc = fmaf(we[k], s_red[k], acc);
        g_gate[n * C_IN + tid] = 1.0f / (1.0f + __expf(-acc));
    }

    grid_barrier();

    // ---------------- Phase 3: scale (block-per-plane, reversed) -------------
    for (int idx = blockIdx.x; idx < PLANES; idx += NBLK) {
        const int plane = (PLANES - 1) - idx;          // L2 tail reuse
        const float g = __ldcg(&g_gate[plane]);

        const float4* p = reinterpret_cast<const float4*>(x   + (size_t)plane * HW);
        float4*       q = reinterpret_cast<float4*>(out       + (size_t)plane * HW);

        #pragma unroll 4
        for (int i = tid; i < HW4; i += TPB) {
            float4 v = p[i];
            v.x *= g; v.y *= g; v.z *= g; v.w *= g;
            __stcs(&q[i], v);
        }
    }
}

// ---------------------------------------------------------------------------
extern "C" void kernel_launch(void* const* d_in, const int* in_sizes, int n_in,
                              void* d_out, int out_size)
{
    const float* x        = (const float*)d_in[0];
    const float* w_reduce = (const float*)d_in[1];
    const float* b_reduce = (const float*)d_in[2];
    const float* w_expand = (const float*)d_in[3];
    const float* b_expand = (const float*)d_in[4];
    float* out = (float*)d_out;

    se_persistent_kernel<<<NBLK, TPB>>>(x, out, w_reduce, b_reduce,
                                        w_expand, b_expand);
}